// round 1
// baseline (speedup 1.0000x reference)
#include <cuda_runtime.h>
#include <cstdint>

#define VV 49152
#define NNZ 9

// ---------------- scratch (device globals; no runtime allocation) ----------------
__device__ float d_T[(size_t)8 * VV * 64];    // block1 Chebyshev terms [k][v*64 + b*32 + f]
__device__ float d_U[(size_t)8 * VV * 128];   // block2 Chebyshev terms [k][v*128 + b*64 + c]; U0 doubles as h1pre
__device__ float d_res[(size_t)2 * VV * 64];  // residual conv output [b][v][o]
__device__ float d_stats[64];                 // [0:32) block1 (sum,sumsq)x16 bins, [32:64) block2

// ---------------- small kernels ----------------
__global__ void k_zero_stats() {
    if (threadIdx.x < 64) d_stats[threadIdx.x] = 0.0f;
}

// T0[v*64 + b*32 + f] = x[b, v, f]
__global__ void k_pack(const float* __restrict__ x) {
    int idx = blockIdx.x * blockDim.x + threadIdx.x;
    if (idx >= VV * 64) return;
    int v = idx >> 6, r = idx & 63, b = r >> 5, f = r & 31;
    d_T[idx] = x[(size_t)b * VV * 32 + (size_t)v * 32 + f];
}

// ---------------- SPMM (Chebyshev recurrence) ----------------
// D = 64 (block1) or 128 (block2). FIRST: tout = L*tin. else: tout = 2*L*tin - tprev2.
template <int D, bool FIRST, bool USE_T>
__global__ void k_spmm(int kin, int kp2, int kout,
                       const float* __restrict__ vals, const int* __restrict__ cols) {
    constexpr int DV = D / 4;
    float* base = USE_T ? d_T : d_U;
    const float4* tin = (const float4*)(base + (size_t)kin * VV * D);
    float4* tout = (float4*)(base + (size_t)kout * VV * D);

    int tid = blockIdx.x * blockDim.x + threadIdx.x;
    if (tid >= VV * DV) return;
    int v = tid / DV, d4 = tid % DV;

    float4 acc = make_float4(0.f, 0.f, 0.f, 0.f);
#pragma unroll
    for (int j = 0; j < NNZ; ++j) {
        int c = __ldg(&cols[v * NNZ + j]);
        float w = __ldg(&vals[v * NNZ + j]);
        float4 t = tin[(size_t)c * DV + d4];
        acc.x += w * t.x; acc.y += w * t.y; acc.z += w * t.z; acc.w += w * t.w;
    }
    if (!FIRST) {
        const float4* tp2 = (const float4*)(base + (size_t)kp2 * VV * D);
        float4 p = tp2[tid];
        acc.x = 2.f * acc.x - p.x; acc.y = 2.f * acc.y - p.y;
        acc.z = 2.f * acc.z - p.z; acc.w = 2.f * acc.w - p.w;
    }
    tout[tid] = acc;
}

// ---------------- GEMM 1: [98304 x 256] @ [256 x 128] (W1 | Wr) ----------------
// Row r = 2*v + b; A(r, kk*32+f) = T[kk][v*64 + b*32 + f].
// cols 0..63 -> h1pre (stored into d_U term 0 as [v*128 + b*64 + o]); 64..127 -> d_res.
__global__ void __launch_bounds__(256) k_gemm1(const float* __restrict__ W1,
                                               const float* __restrict__ Wr,
                                               const float* __restrict__ b1,
                                               const float* __restrict__ br) {
    __shared__ float As[128][33];
    __shared__ float Bs[32][128];
    int v0 = blockIdx.x * 64;
    int tid = threadIdx.x;
    int tx = tid & 15, ty = tid >> 4;
    float acc[8][8];
#pragma unroll
    for (int i = 0; i < 8; ++i)
#pragma unroll
        for (int j = 0; j < 8; ++j) acc[i][j] = 0.f;

    for (int kk = 0; kk < 8; ++kk) {
        // A tile: contiguous 4096 floats of T[kk], rows v0..v0+63
        const float4* src = (const float4*)(d_T + (size_t)kk * VV * 64 + (size_t)v0 * 64);
#pragma unroll
        for (int t = 0; t < 4; ++t) {
            int lt4 = tid + t * 256;
            float4 val = src[lt4];
            int lt = lt4 * 4;
            int voff = lt >> 6, dd = lt & 63, bb = dd >> 5, ff = dd & 31;
            int rr = voff * 2 + bb;
            As[rr][ff] = val.x; As[rr][ff + 1] = val.y;
            As[rr][ff + 2] = val.z; As[rr][ff + 3] = val.w;
        }
        // B tile: Bs[f][o] = (o<64 ? W1 : Wr)[kk, f, o%64]
#pragma unroll
        for (int t = 0; t < 4; ++t) {
            int lt = (tid + t * 256) * 4;
            int f = lt >> 7, o = lt & 127;
            const float* wsrc = (o < 64) ? (W1 + kk * 2048 + f * 64 + o)
                                         : (Wr + kk * 2048 + f * 64 + (o - 64));
            *(float4*)&Bs[f][o] = *(const float4*)wsrc;
        }
        __syncthreads();
#pragma unroll
        for (int f = 0; f < 32; ++f) {
            float a[8];
#pragma unroll
            for (int i = 0; i < 8; ++i) a[i] = As[ty * 8 + i][f];
            float4 bv0 = *(float4*)&Bs[f][tx * 8];
            float4 bv1 = *(float4*)&Bs[f][tx * 8 + 4];
            float bb[8] = {bv0.x, bv0.y, bv0.z, bv0.w, bv1.x, bv1.y, bv1.z, bv1.w};
#pragma unroll
            for (int i = 0; i < 8; ++i)
#pragma unroll
                for (int j = 0; j < 8; ++j) acc[i][j] += a[i] * bb[j];
        }
        __syncthreads();
    }
    // epilogue
#pragma unroll
    for (int i = 0; i < 8; ++i) {
        int rr = ty * 8 + i;
        int v = v0 + (rr >> 1), bb = rr & 1;
#pragma unroll
        for (int j = 0; j < 8; ++j) {
            int o = tx * 8 + j;
            float val = acc[i][j];
            if (o < 64) {
                d_U[(size_t)v * 128 + bb * 64 + o] = val + b1[o];
            } else {
                d_res[(size_t)bb * VV * 64 + (size_t)v * 64 + (o - 64)] = val + br[o - 64];
            }
        }
    }
}

// ---------------- GEMM 2: [98304 x 512] @ [512 x 64] (W2) ----------------
// A(r, kk*64+f) = U[kk][v*128 + b*64 + f]; out -> d_out[b*V*64 + v*64 + o] (h2pre)
__global__ void __launch_bounds__(256) k_gemm2(const float* __restrict__ W2,
                                               const float* __restrict__ b2,
                                               float* __restrict__ out) {
    __shared__ float As[128][65];
    __shared__ float Bs[64][64];
    int v0 = blockIdx.x * 64;
    int tid = threadIdx.x;
    int tx = tid & 15, ty = tid >> 4;
    float acc[8][4];
#pragma unroll
    for (int i = 0; i < 8; ++i)
#pragma unroll
        for (int j = 0; j < 4; ++j) acc[i][j] = 0.f;

    for (int kk = 0; kk < 8; ++kk) {
        const float4* src = (const float4*)(d_U + (size_t)kk * VV * 128 + (size_t)v0 * 128);
#pragma unroll
        for (int t = 0; t < 8; ++t) {
            int lt4 = tid + t * 256;
            float4 val = src[lt4];
            int lt = lt4 * 4;
            int voff = lt >> 7, dd = lt & 127, bb = dd >> 6, ff = dd & 63;
            int rr = voff * 2 + bb;
            As[rr][ff] = val.x; As[rr][ff + 1] = val.y;
            As[rr][ff + 2] = val.z; As[rr][ff + 3] = val.w;
        }
        const float4* wsrc = (const float4*)(W2 + kk * 4096);
#pragma unroll
        for (int t = 0; t < 4; ++t) {
            int lt4 = tid + t * 256;
            int lt = lt4 * 4;
            int f = lt >> 6, o = lt & 63;
            *(float4*)&Bs[f][o] = wsrc[lt4];
        }
        __syncthreads();
#pragma unroll
        for (int f = 0; f < 64; ++f) {
            float a[8];
#pragma unroll
            for (int i = 0; i < 8; ++i) a[i] = As[ty * 8 + i][f];
            float4 bv = *(float4*)&Bs[f][tx * 4];
            float bb[4] = {bv.x, bv.y, bv.z, bv.w};
#pragma unroll
            for (int i = 0; i < 8; ++i)
#pragma unroll
                for (int j = 0; j < 4; ++j) acc[i][j] += a[i] * bb[j];
        }
        __syncthreads();
    }
#pragma unroll
    for (int i = 0; i < 8; ++i) {
        int rr = ty * 8 + i;
        int v = v0 + (rr >> 1), bb = rr & 1;
#pragma unroll
        for (int j = 0; j < 4; ++j) {
            int o = tx * 4 + j;
            out[(size_t)bb * VV * 64 + (size_t)v * 64 + o] = acc[i][j] + b2[o];
        }
    }
}

// ---------------- GroupNorm stats ----------------
// block1: over d_U[0] layout [v*128 + b*64 + c]; bins (b, g=c/8) -> d_stats[0:32)
__global__ void k_stats1() {
    int tid = threadIdx.x;
    int c = tid & 63, b = (tid >> 6) & 1, seg = tid >> 7;
    int v0 = blockIdx.x * 384;
    float s = 0.f, s2 = 0.f;
    for (int v = v0 + seg; v < v0 + 384; v += 2) {
        float x = d_U[(size_t)v * 128 + b * 64 + c];
        s += x; s2 += x * x;
    }
    __shared__ float sm[256], sm2[256];
    sm[tid] = s; sm2[tid] = s2;
    __syncthreads();
    if (tid < 16) {
        int bb = tid >> 3, g = tid & 7;
        float ts = 0.f, ts2 = 0.f;
        for (int seg2 = 0; seg2 < 2; ++seg2)
            for (int cc = 0; cc < 8; ++cc) {
                int t = seg2 * 128 + bb * 64 + g * 8 + cc;
                ts += sm[t]; ts2 += sm2[t];
            }
        atomicAdd(&d_stats[(bb * 8 + g) * 2], ts);
        atomicAdd(&d_stats[(bb * 8 + g) * 2 + 1], ts2);
    }
}

// block2: over h2pre in out[] layout [b*V*64 + v*64 + c]; bins -> d_stats[32:64)
__global__ void k_stats2(const float* __restrict__ H) {
    int tid = threadIdx.x;
    int c = tid & 63, sub = tid >> 6;  // 0..3
    int b = blockIdx.x & 1;
    int v0 = (blockIdx.x >> 1) * 768;
    const float* Hb = H + (size_t)b * VV * 64;
    float s = 0.f, s2 = 0.f;
    for (int v = v0 + sub; v < v0 + 768; v += 4) {
        float x = Hb[(size_t)v * 64 + c];
        s += x; s2 += x * x;
    }
    __shared__ float sm[256], sm2[256];
    sm[tid] = s; sm2[tid] = s2;
    __syncthreads();
    if (tid < 8) {
        int g = tid;
        float ts = 0.f, ts2 = 0.f;
        for (int sub2 = 0; sub2 < 4; ++sub2)
            for (int cc = 0; cc < 8; ++cc) {
                int t = sub2 * 64 + g * 8 + cc;
                ts += sm[t]; ts2 += sm2[t];
            }
        atomicAdd(&d_stats[32 + (b * 8 + g) * 2], ts);
        atomicAdd(&d_stats[32 + (b * 8 + g) * 2 + 1], ts2);
    }
}

// ---------------- GN apply + LeakyReLU ----------------
// block1: in-place on d_U[0] -> becomes U0 for block2 Chebyshev chain
__global__ void k_gnapply1(const float* __restrict__ gamma, const float* __restrict__ beta) {
    int idx = blockIdx.x * blockDim.x + threadIdx.x;
    if (idx >= VV * 128) return;
    int rem = idx & 127, b = rem >> 6, c = rem & 63, g = c >> 3;
    int bin = (b * 8 + g) * 2;
    const float N = (float)(VV * 8);
    float mu = d_stats[bin] / N;
    float var = d_stats[bin + 1] / N - mu * mu;
    float rstd = rsqrtf(var + 1e-5f);
    float y = (d_U[idx] - mu) * rstd * gamma[c] + beta[c];
    d_U[idx] = fmaxf(y, 0.1f * y);
}

// final: out = leaky(gn2(h2pre)) + res, in place on out
__global__ void k_final(float* __restrict__ out,
                        const float* __restrict__ gamma, const float* __restrict__ beta) {
    int idx = blockIdx.x * blockDim.x + threadIdx.x;
    if (idx >= 2 * VV * 64) return;
    int b = idx / (VV * 64);
    int c = idx & 63, g = c >> 3;
    int bin = 32 + (b * 8 + g) * 2;
    const float N = (float)(VV * 8);
    float mu = d_stats[bin] / N;
    float var = d_stats[bin + 1] / N - mu * mu;
    float rstd = rsqrtf(var + 1e-5f);
    float y = (out[idx] - mu) * rstd * gamma[c] + beta[c];
    out[idx] = fmaxf(y, 0.1f * y) + d_res[idx];
}

// ---------------- launch ----------------
extern "C" void kernel_launch(void* const* d_in, const int* in_sizes, int n_in,
                              void* d_out, int out_size) {
    const float* x    = (const float*)d_in[0];
    const float* vals = (const float*)d_in[1];
    // d_in[2] = lap_row (implicit: row = idx/9), unused
    const int*   cols = (const int*)d_in[3];
    const float* W1 = (const float*)d_in[4];
    const float* b1 = (const float*)d_in[5];
    const float* g1 = (const float*)d_in[6];
    const float* be1 = (const float*)d_in[7];
    const float* W2 = (const float*)d_in[8];
    const float* b2 = (const float*)d_in[9];
    const float* g2 = (const float*)d_in[10];
    const float* be2 = (const float*)d_in[11];
    const float* Wr = (const float*)d_in[12];
    const float* br = (const float*)d_in[13];
    float* out = (float*)d_out;

    k_zero_stats<<<1, 64>>>();
    k_pack<<<(VV * 64) / 256, 256>>>(x);

    // block1 + residual Chebyshev terms (D=64): T0..T7
    const int g64 = (VV * 16) / 256;
    k_spmm<64, true, true><<<g64, 256>>>(0, 0, 1, vals, cols);
    k_spmm<64, false, true><<<g64, 256>>>(1, 0, 2, vals, cols);
    k_spmm<64, false, true><<<g64, 256>>>(2, 1, 3, vals, cols);
    k_spmm<64, false, true><<<g64, 256>>>(3, 2, 4, vals, cols);
    k_spmm<64, false, true><<<g64, 256>>>(4, 3, 5, vals, cols);
    k_spmm<64, false, true><<<g64, 256>>>(5, 4, 6, vals, cols);
    k_spmm<64, false, true><<<g64, 256>>>(6, 5, 7, vals, cols);

    // h1pre (into d_U term 0) and residual (d_res)
    k_gemm1<<<VV / 64, 256>>>(W1, Wr, b1, br);

    // GroupNorm 1 + LeakyReLU (in place -> U0)
    k_stats1<<<128, 256>>>();
    k_gnapply1<<<(VV * 128) / 256, 256>>>(g1, be1);

    // block2 Chebyshev terms (D=128): U0..U7
    const int g128 = (VV * 32) / 256;
    k_spmm<128, true, false><<<g128, 256>>>(0, 0, 1, vals, cols);
    k_spmm<128, false, false><<<g128, 256>>>(1, 0, 2, vals, cols);
    k_spmm<128, false, false><<<g128, 256>>>(2, 1, 3, vals, cols);
    k_spmm<128, false, false><<<g128, 256>>>(3, 2, 4, vals, cols);
    k_spmm<128, false, false><<<g128, 256>>>(4, 3, 5, vals, cols);
    k_spmm<128, false, false><<<g128, 256>>>(5, 4, 6, vals, cols);
    k_spmm<128, false, false><<<g128, 256>>>(6, 5, 7, vals, cols);

    // h2pre -> out
    k_gemm2<<<VV / 64, 256>>>(W2, b2, out);

    // GroupNorm 2 + LeakyReLU + residual add (in place on out)
    k_stats2<<<128, 256>>>(out);
    k_final<<<(2 * VV * 64) / 256, 256>>>(out, g2, be2);
}

// round 2
// speedup vs baseline: 1.0003x; 1.0003x over previous
#include <cuda_runtime.h>
#include <cstdint>

#define VV 49152
#define NNZ 9

// ---------------- scratch (device globals; no runtime allocation) ----------------
__device__ float d_T[(size_t)8 * VV * 64];    // block1 Chebyshev terms [k][v*64 + b*32 + f]
__device__ float d_U[(size_t)8 * VV * 128];   // block2 Chebyshev terms [k][v*128 + b*64 + c]; U0 doubles as h1pre
__device__ float d_res[(size_t)2 * VV * 64];  // residual conv output [b][v][o]
__device__ float d_stats[64];                 // [0:32) block1 (sum,sumsq)x16 bins, [32:64) block2

// ---------------- small kernels ----------------
__global__ void k_zero_stats() {
    if (threadIdx.x < 64) d_stats[threadIdx.x] = 0.0f;
}

// T0[v*64 + b*32 + f] = x[b, v, f]
__global__ void k_pack(const float* __restrict__ x) {
    int idx = blockIdx.x * blockDim.x + threadIdx.x;
    if (idx >= VV * 64) return;
    int v = idx >> 6, r = idx & 63, b = r >> 5, f = r & 31;
    d_T[idx] = x[(size_t)b * VV * 32 + (size_t)v * 32 + f];
}

// ---------------- SPMM (Chebyshev recurrence) ----------------
// D = 64 (block1) or 128 (block2). FIRST: tout = L*tin. else: tout = 2*L*tin - tprev2.
template <int D, bool FIRST, bool USE_T>
__global__ void k_spmm(int kin, int kp2, int kout,
                       const float* __restrict__ vals, const int* __restrict__ cols) {
    constexpr int DV = D / 4;
    float* base = USE_T ? d_T : d_U;
    const float4* tin = (const float4*)(base + (size_t)kin * VV * D);
    float4* tout = (float4*)(base + (size_t)kout * VV * D);

    int tid = blockIdx.x * blockDim.x + threadIdx.x;
    if (tid >= VV * DV) return;
    int v = tid / DV, d4 = tid % DV;

    float4 acc = make_float4(0.f, 0.f, 0.f, 0.f);
#pragma unroll
    for (int j = 0; j < NNZ; ++j) {
        int c = __ldg(&cols[v * NNZ + j]);
        float w = __ldg(&vals[v * NNZ + j]);
        float4 t = tin[(size_t)c * DV + d4];
        acc.x += w * t.x; acc.y += w * t.y; acc.z += w * t.z; acc.w += w * t.w;
    }
    if (!FIRST) {
        const float4* tp2 = (const float4*)(base + (size_t)kp2 * VV * D);
        float4 p = tp2[tid];
        acc.x = 2.f * acc.x - p.x; acc.y = 2.f * acc.y - p.y;
        acc.z = 2.f * acc.z - p.z; acc.w = 2.f * acc.w - p.w;
    }
    tout[tid] = acc;
}

// ---------------- GEMM 1: [98304 x 256] @ [256 x 128] (W1 | Wr) ----------------
// Row r = 2*v + b; A(r, kk*32+f) = T[kk][v*64 + b*32 + f].
// cols 0..63 -> h1pre (stored into d_U term 0 as [v*128 + b*64 + o]); 64..127 -> d_res.
__global__ void __launch_bounds__(256) k_gemm1(const float* __restrict__ W1,
                                               const float* __restrict__ Wr,
                                               const float* __restrict__ b1,
                                               const float* __restrict__ br) {
    __shared__ float As[128][33];
    __shared__ float Bs[32][128];
    int v0 = blockIdx.x * 64;
    int tid = threadIdx.x;
    int tx = tid & 15, ty = tid >> 4;
    float acc[8][8];
#pragma unroll
    for (int i = 0; i < 8; ++i)
#pragma unroll
        for (int j = 0; j < 8; ++j) acc[i][j] = 0.f;

    for (int kk = 0; kk < 8; ++kk) {
        // A tile: contiguous 4096 floats of T[kk], rows v0..v0+63
        const float4* src = (const float4*)(d_T + (size_t)kk * VV * 64 + (size_t)v0 * 64);
#pragma unroll
        for (int t = 0; t < 4; ++t) {
            int lt4 = tid + t * 256;
            float4 val = src[lt4];
            int lt = lt4 * 4;
            int voff = lt >> 6, dd = lt & 63, bb = dd >> 5, ff = dd & 31;
            int rr = voff * 2 + bb;
            As[rr][ff] = val.x; As[rr][ff + 1] = val.y;
            As[rr][ff + 2] = val.z; As[rr][ff + 3] = val.w;
        }
        // B tile: Bs[f][o] = (o<64 ? W1 : Wr)[kk, f, o%64]
#pragma unroll
        for (int t = 0; t < 4; ++t) {
            int lt = (tid + t * 256) * 4;
            int f = lt >> 7, o = lt & 127;
            const float* wsrc = (o < 64) ? (W1 + kk * 2048 + f * 64 + o)
                                         : (Wr + kk * 2048 + f * 64 + (o - 64));
            *(float4*)&Bs[f][o] = *(const float4*)wsrc;
        }
        __syncthreads();
#pragma unroll
        for (int f = 0; f < 32; ++f) {
            float a[8];
#pragma unroll
            for (int i = 0; i < 8; ++i) a[i] = As[ty * 8 + i][f];
            float4 bv0 = *(float4*)&Bs[f][tx * 8];
            float4 bv1 = *(float4*)&Bs[f][tx * 8 + 4];
            float bb[8] = {bv0.x, bv0.y, bv0.z, bv0.w, bv1.x, bv1.y, bv1.z, bv1.w};
#pragma unroll
            for (int i = 0; i < 8; ++i)
#pragma unroll
                for (int j = 0; j < 8; ++j) acc[i][j] += a[i] * bb[j];
        }
        __syncthreads();
    }
    // epilogue
#pragma unroll
    for (int i = 0; i < 8; ++i) {
        int rr = ty * 8 + i;
        int v = v0 + (rr >> 1), bb = rr & 1;
#pragma unroll
        for (int j = 0; j < 8; ++j) {
            int o = tx * 8 + j;
            float val = acc[i][j];
            if (o < 64) {
                d_U[(size_t)v * 128 + bb * 64 + o] = val + b1[o];
            } else {
                d_res[(size_t)bb * VV * 64 + (size_t)v * 64 + (o - 64)] = val + br[o - 64];
            }
        }
    }
}

// ---------------- GEMM 2: [98304 x 512] @ [512 x 64] (W2) ----------------
// A(r, kk*64+f) = U[kk][v*128 + b*64 + f]; out -> d_out[b*V*64 + v*64 + o] (h2pre)
__global__ void __launch_bounds__(256) k_gemm2(const float* __restrict__ W2,
                                               const float* __restrict__ b2,
                                               float* __restrict__ out) {
    __shared__ float As[128][65];
    __shared__ float Bs[64][64];
    int v0 = blockIdx.x * 64;
    int tid = threadIdx.x;
    int tx = tid & 15, ty = tid >> 4;
    float acc[8][4];
#pragma unroll
    for (int i = 0; i < 8; ++i)
#pragma unroll
        for (int j = 0; j < 4; ++j) acc[i][j] = 0.f;

    for (int kk = 0; kk < 8; ++kk) {
        const float4* src = (const float4*)(d_U + (size_t)kk * VV * 128 + (size_t)v0 * 128);
#pragma unroll
        for (int t = 0; t < 8; ++t) {
            int lt4 = tid + t * 256;
            float4 val = src[lt4];
            int lt = lt4 * 4;
            int voff = lt >> 7, dd = lt & 127, bb = dd >> 6, ff = dd & 63;
            int rr = voff * 2 + bb;
            As[rr][ff] = val.x; As[rr][ff + 1] = val.y;
            As[rr][ff + 2] = val.z; As[rr][ff + 3] = val.w;
        }
        const float4* wsrc = (const float4*)(W2 + kk * 4096);
#pragma unroll
        for (int t = 0; t < 4; ++t) {
            int lt4 = tid + t * 256;
            int lt = lt4 * 4;
            int f = lt >> 6, o = lt & 63;
            *(float4*)&Bs[f][o] = wsrc[lt4];
        }
        __syncthreads();
#pragma unroll
        for (int f = 0; f < 64; ++f) {
            float a[8];
#pragma unroll
            for (int i = 0; i < 8; ++i) a[i] = As[ty * 8 + i][f];
            float4 bv = *(float4*)&Bs[f][tx * 4];
            float bb[4] = {bv.x, bv.y, bv.z, bv.w};
#pragma unroll
            for (int i = 0; i < 8; ++i)
#pragma unroll
                for (int j = 0; j < 4; ++j) acc[i][j] += a[i] * bb[j];
        }
        __syncthreads();
    }
#pragma unroll
    for (int i = 0; i < 8; ++i) {
        int rr = ty * 8 + i;
        int v = v0 + (rr >> 1), bb = rr & 1;
#pragma unroll
        for (int j = 0; j < 4; ++j) {
            int o = tx * 4 + j;
            out[(size_t)bb * VV * 64 + (size_t)v * 64 + o] = acc[i][j] + b2[o];
        }
    }
}

// ---------------- GroupNorm stats ----------------
// block1: over d_U[0] layout [v*128 + b*64 + c]; bins (b, g=c/8) -> d_stats[0:32)
__global__ void k_stats1() {
    int tid = threadIdx.x;
    int c = tid & 63, b = (tid >> 6) & 1, seg = tid >> 7;
    int v0 = blockIdx.x * 384;
    float s = 0.f, s2 = 0.f;
    for (int v = v0 + seg; v < v0 + 384; v += 2) {
        float x = d_U[(size_t)v * 128 + b * 64 + c];
        s += x; s2 += x * x;
    }
    __shared__ float sm[256], sm2[256];
    sm[tid] = s; sm2[tid] = s2;
    __syncthreads();
    if (tid < 16) {
        int bb = tid >> 3, g = tid & 7;
        float ts = 0.f, ts2 = 0.f;
        for (int seg2 = 0; seg2 < 2; ++seg2)
            for (int cc = 0; cc < 8; ++cc) {
                int t = seg2 * 128 + bb * 64 + g * 8 + cc;
                ts += sm[t]; ts2 += sm2[t];
            }
        atomicAdd(&d_stats[(bb * 8 + g) * 2], ts);
        atomicAdd(&d_stats[(bb * 8 + g) * 2 + 1], ts2);
    }
}

// block2: over h2pre in out[] layout [b*V*64 + v*64 + c]; bins -> d_stats[32:64)
__global__ void k_stats2(const float* __restrict__ H) {
    int tid = threadIdx.x;
    int c = tid & 63, sub = tid >> 6;  // 0..3
    int b = blockIdx.x & 1;
    int v0 = (blockIdx.x >> 1) * 768;
    const float* Hb = H + (size_t)b * VV * 64;
    float s = 0.f, s2 = 0.f;
    for (int v = v0 + sub; v < v0 + 768; v += 4) {
        float x = Hb[(size_t)v * 64 + c];
        s += x; s2 += x * x;
    }
    __shared__ float sm[256], sm2[256];
    sm[tid] = s; sm2[tid] = s2;
    __syncthreads();
    if (tid < 8) {
        int g = tid;
        float ts = 0.f, ts2 = 0.f;
        for (int sub2 = 0; sub2 < 4; ++sub2)
            for (int cc = 0; cc < 8; ++cc) {
                int t = sub2 * 64 + g * 8 + cc;
                ts += sm[t]; ts2 += sm2[t];
            }
        atomicAdd(&d_stats[32 + (b * 8 + g) * 2], ts);
        atomicAdd(&d_stats[32 + (b * 8 + g) * 2 + 1], ts2);
    }
}

// ---------------- GN apply + LeakyReLU ----------------
// block1: in-place on d_U[0] -> becomes U0 for block2 Chebyshev chain
__global__ void k_gnapply1(const float* __restrict__ gamma, const float* __restrict__ beta) {
    int idx = blockIdx.x * blockDim.x + threadIdx.x;
    if (idx >= VV * 128) return;
    int rem = idx & 127, b = rem >> 6, c = rem & 63, g = c >> 3;
    int bin = (b * 8 + g) * 2;
    const float N = (float)(VV * 8);
    float mu = d_stats[bin] / N;
    float var = d_stats[bin + 1] / N - mu * mu;
    float rstd = rsqrtf(var + 1e-5f);
    float y = (d_U[idx] - mu) * rstd * gamma[c] + beta[c];
    d_U[idx] = fmaxf(y, 0.1f * y);
}

// final: out = leaky(gn2(h2pre)) + res, in place on out
__global__ void k_final(float* __restrict__ out,
                        const float* __restrict__ gamma, const float* __restrict__ beta) {
    int idx = blockIdx.x * blockDim.x + threadIdx.x;
    if (idx >= 2 * VV * 64) return;
    int b = idx / (VV * 64);
    int c = idx & 63, g = c >> 3;
    int bin = 32 + (b * 8 + g) * 2;
    const float N = (float)(VV * 8);
    float mu = d_stats[bin] / N;
    float var = d_stats[bin + 1] / N - mu * mu;
    float rstd = rsqrtf(var + 1e-5f);
    float y = (out[idx] - mu) * rstd * gamma[c] + beta[c];
    out[idx] = fmaxf(y, 0.1f * y) + d_res[idx];
}

// ---------------- launch ----------------
extern "C" void kernel_launch(void* const* d_in, const int* in_sizes, int n_in,
                              void* d_out, int out_size) {
    const float* x    = (const float*)d_in[0];
    const float* vals = (const float*)d_in[1];
    // d_in[2] = lap_row (implicit: row = idx/9), unused
    const int*   cols = (const int*)d_in[3];
    const float* W1 = (const float*)d_in[4];
    const float* b1 = (const float*)d_in[5];
    const float* g1 = (const float*)d_in[6];
    const float* be1 = (const float*)d_in[7];
    const float* W2 = (const float*)d_in[8];
    const float* b2 = (const float*)d_in[9];
    const float* g2 = (const float*)d_in[10];
    const float* be2 = (const float*)d_in[11];
    const float* Wr = (const float*)d_in[12];
    const float* br = (const float*)d_in[13];
    float* out = (float*)d_out;

    k_zero_stats<<<1, 64>>>();
    k_pack<<<(VV * 64) / 256, 256>>>(x);

    // block1 + residual Chebyshev terms (D=64): T0..T7
    const int g64 = (VV * 16) / 256;
    k_spmm<64, true, true><<<g64, 256>>>(0, 0, 1, vals, cols);
    k_spmm<64, false, true><<<g64, 256>>>(1, 0, 2, vals, cols);
    k_spmm<64, false, true><<<g64, 256>>>(2, 1, 3, vals, cols);
    k_spmm<64, false, true><<<g64, 256>>>(3, 2, 4, vals, cols);
    k_spmm<64, false, true><<<g64, 256>>>(4, 3, 5, vals, cols);
    k_spmm<64, false, true><<<g64, 256>>>(5, 4, 6, vals, cols);
    k_spmm<64, false, true><<<g64, 256>>>(6, 5, 7, vals, cols);

    // h1pre (into d_U term 0) and residual (d_res)
    k_gemm1<<<VV / 64, 256>>>(W1, Wr, b1, br);

    // GroupNorm 1 + LeakyReLU (in place -> U0)
    k_stats1<<<128, 256>>>();
    k_gnapply1<<<(VV * 128) / 256, 256>>>(g1, be1);

    // block2 Chebyshev terms (D=128): U0..U7
    const int g128 = (VV * 32) / 256;
    k_spmm<128, true, false><<<g128, 256>>>(0, 0, 1, vals, cols);
    k_spmm<128, false, false><<<g128, 256>>>(1, 0, 2, vals, cols);
    k_spmm<128, false, false><<<g128, 256>>>(2, 1, 3, vals, cols);
    k_spmm<128, false, false><<<g128, 256>>>(3, 2, 4, vals, cols);
    k_spmm<128, false, false><<<g128, 256>>>(4, 3, 5, vals, cols);
    k_spmm<128, false, false><<<g128, 256>>>(5, 4, 6, vals, cols);
    k_spmm<128, false, false><<<g128, 256>>>(6, 5, 7, vals, cols);

    // h2pre -> out
    k_gemm2<<<VV / 64, 256>>>(W2, b2, out);

    // GroupNorm 2 + LeakyReLU + residual add (in place on out)
    k_stats2<<<128, 256>>>(out);
    k_final<<<(2 * VV * 64) / 256, 256>>>(out, g2, be2);
}

// round 3
// speedup vs baseline: 1.0067x; 1.0064x over previous
#include <cuda_runtime.h>
#include <cstdint>

#define VV 49152
#define NNZ 9

// ---------------- scratch (device globals; no runtime allocation) ----------------
__device__ float d_T[(size_t)8 * VV * 64];    // block1 Chebyshev terms [k][v*64 + b*32 + f]
__device__ float d_U[(size_t)8 * VV * 128];   // block2 Chebyshev terms [k][v*128 + b*64 + c]; U0 doubles as h1pre
__device__ float d_res[(size_t)2 * VV * 64];  // residual conv output [b][v][o]
__device__ float d_stats[64];                 // [0:32) block1 (sum,sumsq)x16 bins, [32:64) block2

// ---------------- small kernels ----------------
__global__ void k_zero_stats() {
    if (threadIdx.x < 64) d_stats[threadIdx.x] = 0.0f;
}

// T0[v*64 + b*32 + f] = x[b, v, f]
__global__ void k_pack(const float* __restrict__ x) {
    int idx = blockIdx.x * blockDim.x + threadIdx.x;
    if (idx >= VV * 64) return;
    int v = idx >> 6, r = idx & 63, b = r >> 5, f = r & 31;
    d_T[idx] = x[(size_t)b * VV * 32 + (size_t)v * 32 + f];
}

// ---------------- SPMM (Chebyshev recurrence) ----------------
// D = 64 (block1) or 128 (block2). FIRST: tout = L*tin. else: tout = 2*L*tin - tprev2.
template <int D, bool FIRST, bool USE_T>
__global__ void k_spmm(int kin, int kp2, int kout,
                       const float* __restrict__ vals, const int* __restrict__ cols) {
    constexpr int DV = D / 4;
    float* base = USE_T ? d_T : d_U;
    const float4* tin = (const float4*)(base + (size_t)kin * VV * D);
    float4* tout = (float4*)(base + (size_t)kout * VV * D);

    int tid = blockIdx.x * blockDim.x + threadIdx.x;
    if (tid >= VV * DV) return;
    int v = tid / DV, d4 = tid % DV;

    float4 acc = make_float4(0.f, 0.f, 0.f, 0.f);
#pragma unroll
    for (int j = 0; j < NNZ; ++j) {
        int c = __ldg(&cols[v * NNZ + j]);
        float w = __ldg(&vals[v * NNZ + j]);
        float4 t = tin[(size_t)c * DV + d4];
        acc.x += w * t.x; acc.y += w * t.y; acc.z += w * t.z; acc.w += w * t.w;
    }
    if (!FIRST) {
        const float4* tp2 = (const float4*)(base + (size_t)kp2 * VV * D);
        float4 p = tp2[tid];
        acc.x = 2.f * acc.x - p.x; acc.y = 2.f * acc.y - p.y;
        acc.z = 2.f * acc.z - p.z; acc.w = 2.f * acc.w - p.w;
    }
    tout[tid] = acc;
}

// ---------------- GEMM 1: [98304 x 256] @ [256 x 128] (W1 | Wr) ----------------
// Row r = 2*v + b; A(r, kk*32+f) = T[kk][v*64 + b*32 + f].
// cols 0..63 -> h1pre (stored into d_U term 0 as [v*128 + b*64 + o]); 64..127 -> d_res.
__global__ void __launch_bounds__(256) k_gemm1(const float* __restrict__ W1,
                                               const float* __restrict__ Wr,
                                               const float* __restrict__ b1,
                                               const float* __restrict__ br) {
    __shared__ float As[128][33];
    __shared__ float Bs[32][128];
    int v0 = blockIdx.x * 64;
    int tid = threadIdx.x;
    int tx = tid & 15, ty = tid >> 4;
    float acc[8][8];
#pragma unroll
    for (int i = 0; i < 8; ++i)
#pragma unroll
        for (int j = 0; j < 8; ++j) acc[i][j] = 0.f;

    for (int kk = 0; kk < 8; ++kk) {
        // A tile: contiguous 4096 floats of T[kk], rows v0..v0+63
        const float4* src = (const float4*)(d_T + (size_t)kk * VV * 64 + (size_t)v0 * 64);
#pragma unroll
        for (int t = 0; t < 4; ++t) {
            int lt4 = tid + t * 256;
            float4 val = src[lt4];
            int lt = lt4 * 4;
            int voff = lt >> 6, dd = lt & 63, bb = dd >> 5, ff = dd & 31;
            int rr = voff * 2 + bb;
            As[rr][ff] = val.x; As[rr][ff + 1] = val.y;
            As[rr][ff + 2] = val.z; As[rr][ff + 3] = val.w;
        }
        // B tile: Bs[f][o] = (o<64 ? W1 : Wr)[kk, f, o%64]
#pragma unroll
        for (int t = 0; t < 4; ++t) {
            int lt = (tid + t * 256) * 4;
            int f = lt >> 7, o = lt & 127;
            const float* wsrc = (o < 64) ? (W1 + kk * 2048 + f * 64 + o)
                                         : (Wr + kk * 2048 + f * 64 + (o - 64));
            *(float4*)&Bs[f][o] = *(const float4*)wsrc;
        }
        __syncthreads();
#pragma unroll
        for (int f = 0; f < 32; ++f) {
            float a[8];
#pragma unroll
            for (int i = 0; i < 8; ++i) a[i] = As[ty * 8 + i][f];
            float4 bv0 = *(float4*)&Bs[f][tx * 8];
            float4 bv1 = *(float4*)&Bs[f][tx * 8 + 4];
            float bb[8] = {bv0.x, bv0.y, bv0.z, bv0.w, bv1.x, bv1.y, bv1.z, bv1.w};
#pragma unroll
            for (int i = 0; i < 8; ++i)
#pragma unroll
                for (int j = 0; j < 8; ++j) acc[i][j] += a[i] * bb[j];
        }
        __syncthreads();
    }
    // epilogue
#pragma unroll
    for (int i = 0; i < 8; ++i) {
        int rr = ty * 8 + i;
        int v = v0 + (rr >> 1), bb = rr & 1;
#pragma unroll
        for (int j = 0; j < 8; ++j) {
            int o = tx * 8 + j;
            float val = acc[i][j];
            if (o < 64) {
                d_U[(size_t)v * 128 + bb * 64 + o] = val + b1[o];
            } else {
                d_res[(size_t)bb * VV * 64 + (size_t)v * 64 + (o - 64)] = val + br[o - 64];
            }
        }
    }
}

// ---------------- GEMM 2: [98304 x 512] @ [512 x 64] (W2) ----------------
// A(r, kk*64+f) = U[kk][v*128 + b*64 + f]; out -> d_out[b*V*64 + v*64 + o] (h2pre)
__global__ void __launch_bounds__(256) k_gemm2(const float* __restrict__ W2,
                                               const float* __restrict__ b2,
                                               float* __restrict__ out) {
    __shared__ float As[128][65];
    __shared__ float Bs[64][64];
    int v0 = blockIdx.x * 64;
    int tid = threadIdx.x;
    int tx = tid & 15, ty = tid >> 4;
    float acc[8][4];
#pragma unroll
    for (int i = 0; i < 8; ++i)
#pragma unroll
        for (int j = 0; j < 4; ++j) acc[i][j] = 0.f;

    for (int kk = 0; kk < 8; ++kk) {
        const float4* src = (const float4*)(d_U + (size_t)kk * VV * 128 + (size_t)v0 * 128);
#pragma unroll
        for (int t = 0; t < 8; ++t) {
            int lt4 = tid + t * 256;
            float4 val = src[lt4];
            int lt = lt4 * 4;
            int voff = lt >> 7, dd = lt & 127, bb = dd >> 6, ff = dd & 63;
            int rr = voff * 2 + bb;
            As[rr][ff] = val.x; As[rr][ff + 1] = val.y;
            As[rr][ff + 2] = val.z; As[rr][ff + 3] = val.w;
        }
        const float4* wsrc = (const float4*)(W2 + kk * 4096);
#pragma unroll
        for (int t = 0; t < 4; ++t) {
            int lt4 = tid + t * 256;
            int lt = lt4 * 4;
            int f = lt >> 6, o = lt & 63;
            *(float4*)&Bs[f][o] = wsrc[lt4];
        }
        __syncthreads();
#pragma unroll
        for (int f = 0; f < 64; ++f) {
            float a[8];
#pragma unroll
            for (int i = 0; i < 8; ++i) a[i] = As[ty * 8 + i][f];
            float4 bv = *(float4*)&Bs[f][tx * 4];
            float bb[4] = {bv.x, bv.y, bv.z, bv.w};
#pragma unroll
            for (int i = 0; i < 8; ++i)
#pragma unroll
                for (int j = 0; j < 4; ++j) acc[i][j] += a[i] * bb[j];
        }
        __syncthreads();
    }
#pragma unroll
    for (int i = 0; i < 8; ++i) {
        int rr = ty * 8 + i;
        int v = v0 + (rr >> 1), bb = rr & 1;
#pragma unroll
        for (int j = 0; j < 4; ++j) {
            int o = tx * 4 + j;
            out[(size_t)bb * VV * 64 + (size_t)v * 64 + o] = acc[i][j] + b2[o];
        }
    }
}

// ---------------- GroupNorm stats ----------------
// block1: over d_U[0] layout [v*128 + b*64 + c]; bins (b, g=c/8) -> d_stats[0:32)
__global__ void k_stats1() {
    int tid = threadIdx.x;
    int c = tid & 63, b = (tid >> 6) & 1, seg = tid >> 7;
    int v0 = blockIdx.x * 384;
    float s = 0.f, s2 = 0.f;
    for (int v = v0 + seg; v < v0 + 384; v += 2) {
        float x = d_U[(size_t)v * 128 + b * 64 + c];
        s += x; s2 += x * x;
    }
    __shared__ float sm[256], sm2[256];
    sm[tid] = s; sm2[tid] = s2;
    __syncthreads();
    if (tid < 16) {
        int bb = tid >> 3, g = tid & 7;
        float ts = 0.f, ts2 = 0.f;
        for (int seg2 = 0; seg2 < 2; ++seg2)
            for (int cc = 0; cc < 8; ++cc) {
                int t = seg2 * 128 + bb * 64 + g * 8 + cc;
                ts += sm[t]; ts2 += sm2[t];
            }
        atomicAdd(&d_stats[(bb * 8 + g) * 2], ts);
        atomicAdd(&d_stats[(bb * 8 + g) * 2 + 1], ts2);
    }
}

// block2: over h2pre in out[] layout [b*V*64 + v*64 + c]; bins -> d_stats[32:64)
__global__ void k_stats2(const float* __restrict__ H) {
    int tid = threadIdx.x;
    int c = tid & 63, sub = tid >> 6;  // 0..3
    int b = blockIdx.x & 1;
    int v0 = (blockIdx.x >> 1) * 768;
    const float* Hb = H + (size_t)b * VV * 64;
    float s = 0.f, s2 = 0.f;
    for (int v = v0 + sub; v < v0 + 768; v += 4) {
        float x = Hb[(size_t)v * 64 + c];
        s += x; s2 += x * x;
    }
    __shared__ float sm[256], sm2[256];
    sm[tid] = s; sm2[tid] = s2;
    __syncthreads();
    if (tid < 8) {
        int g = tid;
        float ts = 0.f, ts2 = 0.f;
        for (int sub2 = 0; sub2 < 4; ++sub2)
            for (int cc = 0; cc < 8; ++cc) {
                int t = sub2 * 64 + g * 8 + cc;
                ts += sm[t]; ts2 += sm2[t];
            }
        atomicAdd(&d_stats[32 + (b * 8 + g) * 2], ts);
        atomicAdd(&d_stats[32 + (b * 8 + g) * 2 + 1], ts2);
    }
}

// ---------------- GN apply + LeakyReLU ----------------
// block1: in-place on d_U[0] -> becomes U0 for block2 Chebyshev chain
__global__ void k_gnapply1(const float* __restrict__ gamma, const float* __restrict__ beta) {
    int idx = blockIdx.x * blockDim.x + threadIdx.x;
    if (idx >= VV * 128) return;
    int rem = idx & 127, b = rem >> 6, c = rem & 63, g = c >> 3;
    int bin = (b * 8 + g) * 2;
    const float N = (float)(VV * 8);
    float mu = d_stats[bin] / N;
    float var = d_stats[bin + 1] / N - mu * mu;
    float rstd = rsqrtf(var + 1e-5f);
    float y = (d_U[idx] - mu) * rstd * gamma[c] + beta[c];
    d_U[idx] = fmaxf(y, 0.1f * y);
}

// final: out = leaky(gn2(h2pre)) + res, in place on out
__global__ void k_final(float* __restrict__ out,
                        const float* __restrict__ gamma, const float* __restrict__ beta) {
    int idx = blockIdx.x * blockDim.x + threadIdx.x;
    if (idx >= 2 * VV * 64) return;
    int b = idx / (VV * 64);
    int c = idx & 63, g = c >> 3;
    int bin = 32 + (b * 8 + g) * 2;
    const float N = (float)(VV * 8);
    float mu = d_stats[bin] / N;
    float var = d_stats[bin + 1] / N - mu * mu;
    float rstd = rsqrtf(var + 1e-5f);
    float y = (out[idx] - mu) * rstd * gamma[c] + beta[c];
    out[idx] = fmaxf(y, 0.1f * y) + d_res[idx];
}

// ---------------- launch ----------------
extern "C" void kernel_launch(void* const* d_in, const int* in_sizes, int n_in,
                              void* d_out, int out_size) {
    const float* x    = (const float*)d_in[0];
    const float* vals = (const float*)d_in[1];
    // d_in[2] = lap_row (implicit: row = idx/9), unused
    const int*   cols = (const int*)d_in[3];
    const float* W1 = (const float*)d_in[4];
    const float* b1 = (const float*)d_in[5];
    const float* g1 = (const float*)d_in[6];
    const float* be1 = (const float*)d_in[7];
    const float* W2 = (const float*)d_in[8];
    const float* b2 = (const float*)d_in[9];
    const float* g2 = (const float*)d_in[10];
    const float* be2 = (const float*)d_in[11];
    const float* Wr = (const float*)d_in[12];
    const float* br = (const float*)d_in[13];
    float* out = (float*)d_out;

    k_zero_stats<<<1, 64>>>();
    k_pack<<<(VV * 64) / 256, 256>>>(x);

    // block1 + residual Chebyshev terms (D=64): T0..T7
    const int g64 = (VV * 16) / 256;
    k_spmm<64, true, true><<<g64, 256>>>(0, 0, 1, vals, cols);
    k_spmm<64, false, true><<<g64, 256>>>(1, 0, 2, vals, cols);
    k_spmm<64, false, true><<<g64, 256>>>(2, 1, 3, vals, cols);
    k_spmm<64, false, true><<<g64, 256>>>(3, 2, 4, vals, cols);
    k_spmm<64, false, true><<<g64, 256>>>(4, 3, 5, vals, cols);
    k_spmm<64, false, true><<<g64, 256>>>(5, 4, 6, vals, cols);
    k_spmm<64, false, true><<<g64, 256>>>(6, 5, 7, vals, cols);

    // h1pre (into d_U term 0) and residual (d_res)
    k_gemm1<<<VV / 64, 256>>>(W1, Wr, b1, br);

    // GroupNorm 1 + LeakyReLU (in place -> U0)
    k_stats1<<<128, 256>>>();
    k_gnapply1<<<(VV * 128) / 256, 256>>>(g1, be1);

    // block2 Chebyshev terms (D=128): U0..U7
    const int g128 = (VV * 32) / 256;
    k_spmm<128, true, false><<<g128, 256>>>(0, 0, 1, vals, cols);
    k_spmm<128, false, false><<<g128, 256>>>(1, 0, 2, vals, cols);
    k_spmm<128, false, false><<<g128, 256>>>(2, 1, 3, vals, cols);
    k_spmm<128, false, false><<<g128, 256>>>(3, 2, 4, vals, cols);
    k_spmm<128, false, false><<<g128, 256>>>(4, 3, 5, vals, cols);
    k_spmm<128, false, false><<<g128, 256>>>(5, 4, 6, vals, cols);
    k_spmm<128, false, false><<<g128, 256>>>(6, 5, 7, vals, cols);

    // h2pre -> out
    k_gemm2<<<VV / 64, 256>>>(W2, b2, out);

    // GroupNorm 2 + LeakyReLU + residual add (in place on out)
    k_stats2<<<128, 256>>>(out);
    k_final<<<(2 * VV * 64) / 256, 256>>>(out, g2, be2);
}

// round 6
// speedup vs baseline: 1.4538x; 1.4442x over previous
#include <cuda_runtime.h>
#include <cstdint>

#define VV 49152
#define NNZ 9

// ---------------- scratch (device globals; no runtime allocation) ----------------
__device__ float d_T[(size_t)8 * VV * 64];    // block1 Chebyshev terms [k][v*64 + b*32 + f]
__device__ float d_U[(size_t)8 * VV * 128];   // block2 Chebyshev terms [k][v*128 + b*64 + c]; U0 = h1
__device__ float d_res[(size_t)2 * VV * 64];  // residual conv output [b][v][o]
__device__ float d_stats[64];                 // (sum,sumsq) bins
__device__ float d_Bt1[8 * 128 * 32];         // GEMM1 B^T: [kk][o(0..127)][f(0..31)]  (W1|Wr), tf32-rounded
__device__ float d_Bt2[16 * 64 * 32];         // GEMM2 B^T: [chunk][o(0..63)][f'(0..31)] (W2), tf32-rounded

// ---------------- helpers ----------------
__device__ __forceinline__ float ftf32(float x) {
    uint32_t r;
    asm("cvt.rna.tf32.f32 %0, %1;" : "=r"(r) : "f"(x));
    return __uint_as_float(r);
}
__device__ __forceinline__ void mma_tf32(float* d, uint32_t a0, uint32_t a1, uint32_t a2,
                                         uint32_t a3, uint32_t b0, uint32_t b1) {
    asm volatile(
        "mma.sync.aligned.m16n8k8.row.col.f32.tf32.tf32.f32 "
        "{%0,%1,%2,%3}, {%4,%5,%6,%7}, {%8,%9}, {%0,%1,%2,%3};"
        : "+f"(d[0]), "+f"(d[1]), "+f"(d[2]), "+f"(d[3])
        : "r"(a0), "r"(a1), "r"(a2), "r"(a3), "r"(b0), "r"(b1));
}

// ---------------- small kernels ----------------
__global__ void k_zero_stats() {
    if (threadIdx.x < 64) d_stats[threadIdx.x] = 0.0f;
}

__global__ void k_pack(const float* __restrict__ x) {
    int idx = blockIdx.x * blockDim.x + threadIdx.x;
    if (idx >= VV * 64) return;
    int v = idx >> 6, r = idx & 63, b = r >> 5, f = r & 31;
    d_T[idx] = x[(size_t)b * VV * 32 + (size_t)v * 32 + f];
}

// Pre-transpose weights into [o][k] layout (coalesced B-tile loads), tf32-rounded.
__global__ void k_wtrans(const float* __restrict__ W1, const float* __restrict__ Wr,
                         const float* __restrict__ W2) {
    int idx = blockIdx.x * blockDim.x + threadIdx.x;
    if (idx < 8 * 128 * 32) {
        int kk = idx >> 12, r = idx & 4095, o = r >> 5, f = r & 31;
        float w = (o < 64) ? W1[kk * 2048 + f * 64 + o] : Wr[kk * 2048 + f * 64 + (o - 64)];
        d_Bt1[idx] = ftf32(w);
    } else if (idx < 8 * 128 * 32 + 16 * 64 * 32) {
        int j = idx - 8 * 128 * 32;
        int c = j >> 11, rr = j & 2047, o = rr >> 5, f = rr & 31;
        int kk = c >> 1, f0 = (c & 1) * 32;
        d_Bt2[j] = ftf32(W2[kk * 4096 + (f0 + f) * 64 + o]);
    }
}

// ---------------- SPMM (Chebyshev recurrence): 8 floats / thread ----------------
template <int D, bool FIRST, bool USE_T>
__global__ void __launch_bounds__(256) k_spmm(int kin, int kp2, int kout,
                                              const float* __restrict__ vals,
                                              const int* __restrict__ cols) {
    constexpr int TPR = D / 8;  // threads per row
    int tid = blockIdx.x * 256 + threadIdx.x;
    if (tid >= VV * TPR) return;
    int v = tid / TPR, d8 = tid % TPR;
    float* base = USE_T ? d_T : d_U;
    const float4* __restrict__ tin = (const float4*)(base + (size_t)kin * VV * D);
    float4* tout = (float4*)(base + (size_t)kout * VV * D);

    int off[NNZ];
    float w[NNZ];
#pragma unroll
    for (int j = 0; j < NNZ; ++j) {
        w[j] = __ldg(&vals[v * NNZ + j]);
        off[j] = __ldg(&cols[v * NNZ + j]) * (D / 4) + d8 * 2;
    }
    float4 a0 = make_float4(0.f, 0.f, 0.f, 0.f);
    float4 a1 = make_float4(0.f, 0.f, 0.f, 0.f);
#pragma unroll
    for (int j = 0; j < NNZ; ++j) {
        float4 t0 = __ldg(&tin[off[j]]);
        float4 t1 = __ldg(&tin[off[j] + 1]);
        a0.x += w[j] * t0.x; a0.y += w[j] * t0.y; a0.z += w[j] * t0.z; a0.w += w[j] * t0.w;
        a1.x += w[j] * t1.x; a1.y += w[j] * t1.y; a1.z += w[j] * t1.z; a1.w += w[j] * t1.w;
    }
    size_t oidx = (size_t)v * (D / 4) + d8 * 2;
    if (!FIRST) {
        const float4* tp2 = (const float4*)(base + (size_t)kp2 * VV * D);
        float4 p0 = tp2[oidx], p1 = tp2[oidx + 1];
        a0.x = 2.f * a0.x - p0.x; a0.y = 2.f * a0.y - p0.y;
        a0.z = 2.f * a0.z - p0.z; a0.w = 2.f * a0.w - p0.w;
        a1.x = 2.f * a1.x - p1.x; a1.y = 2.f * a1.y - p1.y;
        a1.z = 2.f * a1.z - p1.z; a1.w = 2.f * a1.w - p1.w;
    }
    tout[oidx] = a0;
    tout[oidx + 1] = a1;
}

// ---------------- mma.sync tf32 GEMM 1: [98304 x 256] @ [256 x 128] (W1 | Wr) ----------------
// Block tile 128(M) x 128(N), BK=32 (one cheb term per chunk, 8 chunks).
// Row r = 2*v + b. Cols 0..63 -> d_U(+b1); 64..127 -> d_res(+br).
__global__ void __launch_bounds__(256) k_gemm1_mma(const float* __restrict__ b1,
                                                   const float* __restrict__ br) {
    __shared__ float As[128][36];
    __shared__ float Bs[128][36];
    int v0 = blockIdx.x * 64;
    int tid = threadIdx.x;
    int warp = tid >> 5, lane = tid & 31;
    int g = lane >> 2, t = lane & 3;
    int wm = warp >> 1, wn = warp & 1;         // 4 x 2 warps
    int m_w = wm * 32, n_w = wn * 64;

    float acc[2][8][4];
#pragma unroll
    for (int mi = 0; mi < 2; ++mi)
#pragma unroll
        for (int ni = 0; ni < 8; ++ni)
#pragma unroll
            for (int q = 0; q < 4; ++q) acc[mi][ni][q] = 0.f;

#pragma unroll 1
    for (int c = 0; c < 8; ++c) {
        // stage A: 128 rows x 32 k (tf32-round on the fly)
        const float4* asrc = (const float4*)(d_T + (size_t)c * VV * 64 + (size_t)v0 * 64);
#pragma unroll
        for (int tl = 0; tl < 4; ++tl) {
            int lt4 = tid + tl * 256;
            float4 val = asrc[lt4];
            val.x = ftf32(val.x); val.y = ftf32(val.y);
            val.z = ftf32(val.z); val.w = ftf32(val.w);
            int lt = lt4 * 4;
            int r = ((lt >> 6) << 1) | ((lt >> 5) & 1);
            int f = lt & 31;
            *(float4*)&As[r][f] = val;
        }
        // stage B: 128 o x 32 k (already tf32)
        const float4* bsrc = (const float4*)(d_Bt1 + c * 4096);
#pragma unroll
        for (int tl = 0; tl < 4; ++tl) {
            int lt4 = tid + tl * 256;
            float4 val = bsrc[lt4];
            int lt = lt4 * 4;
            *(float4*)&Bs[lt >> 5][lt & 31] = val;
        }
        __syncthreads();
#pragma unroll
        for (int ks = 0; ks < 4; ++ks) {
            int k0 = ks * 8;
            uint32_t a[2][4];
#pragma unroll
            for (int mi = 0; mi < 2; ++mi) {
                int m = m_w + mi * 16;
                a[mi][0] = __float_as_uint(As[m + g][k0 + t]);
                a[mi][1] = __float_as_uint(As[m + g + 8][k0 + t]);
                a[mi][2] = __float_as_uint(As[m + g][k0 + t + 4]);
                a[mi][3] = __float_as_uint(As[m + g + 8][k0 + t + 4]);
            }
#pragma unroll
            for (int ni = 0; ni < 8; ++ni) {
                int n = n_w + ni * 8;
                uint32_t b0 = __float_as_uint(Bs[n + g][k0 + t]);
                uint32_t b1v = __float_as_uint(Bs[n + g][k0 + t + 4]);
#pragma unroll
                for (int mi = 0; mi < 2; ++mi)
                    mma_tf32(acc[mi][ni], a[mi][0], a[mi][1], a[mi][2], a[mi][3], b0, b1v);
            }
        }
        __syncthreads();
    }
    // epilogue: D[r1][n..n+1] = (c0,c1), D[r1+8][n..n+1] = (c2,c3)
#pragma unroll
    for (int mi = 0; mi < 2; ++mi) {
        int r1 = m_w + mi * 16 + g;
        int v1 = v0 + (r1 >> 1), bb1 = r1 & 1;
        int r2 = r1 + 8;
        int v2 = v0 + (r2 >> 1), bb2 = r2 & 1;
#pragma unroll
        for (int ni = 0; ni < 8; ++ni) {
            int n = n_w + ni * 8 + t * 2;
            float2 p1 = make_float2(acc[mi][ni][0], acc[mi][ni][1]);
            float2 p2 = make_float2(acc[mi][ni][2], acc[mi][ni][3]);
            if (n < 64) {
                p1.x += __ldg(&b1[n]); p1.y += __ldg(&b1[n + 1]);
                p2.x += __ldg(&b1[n]); p2.y += __ldg(&b1[n + 1]);
                *(float2*)(d_U + (size_t)v1 * 128 + bb1 * 64 + n) = p1;
                *(float2*)(d_U + (size_t)v2 * 128 + bb2 * 64 + n) = p2;
            } else {
                int o = n - 64;
                p1.x += __ldg(&br[o]); p1.y += __ldg(&br[o + 1]);
                p2.x += __ldg(&br[o]); p2.y += __ldg(&br[o + 1]);
                *(float2*)(d_res + (size_t)bb1 * VV * 64 + (size_t)v1 * 64 + o) = p1;
                *(float2*)(d_res + (size_t)bb2 * VV * 64 + (size_t)v2 * 64 + o) = p2;
            }
        }
    }
}

// ---------------- mma.sync tf32 GEMM 2: [98304 x 512] @ [512 x 64] (W2) ----------------
// Block tile 128(M) x 64(N), BK=32 (16 chunks: kk=c>>1, f0=(c&1)*32). Out = h2pre(+b2).
__global__ void __launch_bounds__(256) k_gemm2_mma(const float* __restrict__ b2,
                                                   float* __restrict__ out) {
    __shared__ float As[128][36];
    __shared__ float Bs[64][36];
    int v0 = blockIdx.x * 64;
    int tid = threadIdx.x;
    int warp = tid >> 5, lane = tid & 31;
    int g = lane >> 2, t = lane & 3;
    int m_w = warp * 16;                        // 8 warps along M

    float acc[8][4];
#pragma unroll
    for (int ni = 0; ni < 8; ++ni)
#pragma unroll
        for (int q = 0; q < 4; ++q) acc[ni][q] = 0.f;

#pragma unroll 1
    for (int c = 0; c < 16; ++c) {
        int kk = c >> 1, f0 = (c & 1) * 32;
        const float4* asrc = (const float4*)(d_U + (size_t)kk * VV * 128 + (size_t)v0 * 128 + f0);
#pragma unroll
        for (int tl = 0; tl < 4; ++tl) {
            int lt4 = tid + tl * 256;
            int r = lt4 >> 3;                   // 0..127
            int f4 = lt4 & 7;                   // float4 index within 32 floats
            float4 val = asrc[(r >> 1) * 32 + (r & 1) * 16 + f4];
            val.x = ftf32(val.x); val.y = ftf32(val.y);
            val.z = ftf32(val.z); val.w = ftf32(val.w);
            *(float4*)&As[r][f4 * 4] = val;
        }
        const float4* bsrc = (const float4*)(d_Bt2 + c * 2048);
#pragma unroll
        for (int tl = 0; tl < 2; ++tl) {
            int lt4 = tid + tl * 256;
            float4 val = bsrc[lt4];
            int lt = lt4 * 4;
            *(float4*)&Bs[lt >> 5][lt & 31] = val;
        }
        __syncthreads();
#pragma unroll
        for (int ks = 0; ks < 4; ++ks) {
            int k0 = ks * 8;
            uint32_t a0 = __float_as_uint(As[m_w + g][k0 + t]);
            uint32_t a1 = __float_as_uint(As[m_w + g + 8][k0 + t]);
            uint32_t a2 = __float_as_uint(As[m_w + g][k0 + t + 4]);
            uint32_t a3 = __float_as_uint(As[m_w + g + 8][k0 + t + 4]);
#pragma unroll
            for (int ni = 0; ni < 8; ++ni) {
                int n = ni * 8;
                uint32_t b0 = __float_as_uint(Bs[n + g][k0 + t]);
                uint32_t b1v = __float_as_uint(Bs[n + g][k0 + t + 4]);
                mma_tf32(acc[ni], a0, a1, a2, a3, b0, b1v);
            }
        }
        __syncthreads();
    }
    int r1 = m_w + g;
    int v1 = v0 + (r1 >> 1), bb1 = r1 & 1;
    int r2 = r1 + 8;
    int v2 = v0 + (r2 >> 1), bb2 = r2 & 1;
    float* o1 = out + (size_t)bb1 * VV * 64 + (size_t)v1 * 64;
    float* o2 = out + (size_t)bb2 * VV * 64 + (size_t)v2 * 64;
#pragma unroll
    for (int ni = 0; ni < 8; ++ni) {
        int n = ni * 8 + t * 2;
        float bx = __ldg(&b2[n]), by = __ldg(&b2[n + 1]);
        *(float2*)(o1 + n) = make_float2(acc[ni][0] + bx, acc[ni][1] + by);
        *(float2*)(o2 + n) = make_float2(acc[ni][2] + bx, acc[ni][3] + by);
    }
}

// ---------------- GroupNorm stats ----------------
__global__ void k_stats1() {
    int tid = threadIdx.x;
    int c = tid & 63, b = (tid >> 6) & 1, seg = tid >> 7;
    int v0 = blockIdx.x * 384;
    float s = 0.f, s2 = 0.f;
    for (int v = v0 + seg; v < v0 + 384; v += 2) {
        float x = d_U[(size_t)v * 128 + b * 64 + c];
        s += x; s2 += x * x;
    }
    __shared__ float sm[256], sm2[256];
    sm[tid] = s; sm2[tid] = s2;
    __syncthreads();
    if (tid < 16) {
        int bb = tid >> 3, g = tid & 7;
        float ts = 0.f, ts2 = 0.f;
        for (int seg2 = 0; seg2 < 2; ++seg2)
            for (int cc = 0; cc < 8; ++cc) {
                int t = seg2 * 128 + bb * 64 + g * 8 + cc;
                ts += sm[t]; ts2 += sm2[t];
            }
        atomicAdd(&d_stats[(bb * 8 + g) * 2], ts);
        atomicAdd(&d_stats[(bb * 8 + g) * 2 + 1], ts2);
    }
}

__global__ void k_stats2(const float* __restrict__ H) {
    int tid = threadIdx.x;
    int c = tid & 63, sub = tid >> 6;
    int b = blockIdx.x & 1;
    int v0 = (blockIdx.x >> 1) * 768;
    const float* Hb = H + (size_t)b * VV * 64;
    float s = 0.f, s2 = 0.f;
    for (int v = v0 + sub; v < v0 + 768; v += 4) {
        float x = Hb[(size_t)v * 64 + c];
        s += x; s2 += x * x;
    }
    __shared__ float sm[256], sm2[256];
    sm[tid] = s; sm2[tid] = s2;
    __syncthreads();
    if (tid < 8) {
        int g = tid;
        float ts = 0.f, ts2 = 0.f;
        for (int sub2 = 0; sub2 < 4; ++sub2)
            for (int cc = 0; cc < 8; ++cc) {
                int t = sub2 * 64 + g * 8 + cc;
                ts += sm[t]; ts2 += sm2[t];
            }
        atomicAdd(&d_stats[32 + (b * 8 + g) * 2], ts);
        atomicAdd(&d_stats[32 + (b * 8 + g) * 2 + 1], ts2);
    }
}

// ---------------- GN apply + LeakyReLU ----------------
__global__ void k_gnapply1(const float* __restrict__ gamma, const float* __restrict__ beta) {
    int idx = blockIdx.x * blockDim.x + threadIdx.x;
    if (idx >= VV * 128) return;
    int rem = idx & 127, b = rem >> 6, c = rem & 63, g = c >> 3;
    int bin = (b * 8 + g) * 2;
    const float N = (float)(VV * 8);
    float mu = d_stats[bin] / N;
    float var = d_stats[bin + 1] / N - mu * mu;
    float rstd = rsqrtf(var + 1e-5f);
    float y = (d_U[idx] - mu) * rstd * gamma[c] + beta[c];
    d_U[idx] = fmaxf(y, 0.1f * y);
}

__global__ void k_final(float* __restrict__ out,
                        const float* __restrict__ gamma, const float* __restrict__ beta) {
    int idx = blockIdx.x * blockDim.x + threadIdx.x;
    if (idx >= 2 * VV * 64) return;
    int b = idx / (VV * 64);
    int c = idx & 63, g = c >> 3;
    int bin = 32 + (b * 8 + g) * 2;
    const float N = (float)(VV * 8);
    float mu = d_stats[bin] / N;
    float var = d_stats[bin + 1] / N - mu * mu;
    float rstd = rsqrtf(var + 1e-5f);
    float y = (out[idx] - mu) * rstd * gamma[c] + beta[c];
    out[idx] = fmaxf(y, 0.1f * y) + d_res[idx];
}

// ---------------- launch ----------------
extern "C" void kernel_launch(void* const* d_in, const int* in_sizes, int n_in,
                              void* d_out, int out_size) {
    const float* x    = (const float*)d_in[0];
    const float* vals = (const float*)d_in[1];
    const int*   cols = (const int*)d_in[3];
    const float* W1 = (const float*)d_in[4];
    const float* b1 = (const float*)d_in[5];
    const float* g1 = (const float*)d_in[6];
    const float* be1 = (const float*)d_in[7];
    const float* W2 = (const float*)d_in[8];
    const float* b2 = (const float*)d_in[9];
    const float* g2 = (const float*)d_in[10];
    const float* be2 = (const float*)d_in[11];
    const float* Wr = (const float*)d_in[12];
    const float* br = (const float*)d_in[13];
    float* out = (float*)d_out;

    k_zero_stats<<<1, 64>>>();
    k_pack<<<(VV * 64) / 256, 256>>>(x);
    k_wtrans<<<(8 * 128 * 32 + 16 * 64 * 32) / 256, 256>>>(W1, Wr, W2);

    // block1 + residual Chebyshev terms (D=64): T0..T7
    const int g64 = (VV * 8) / 256;
    k_spmm<64, true, true><<<g64, 256>>>(0, 0, 1, vals, cols);
    k_spmm<64, false, true><<<g64, 256>>>(1, 0, 2, vals, cols);
    k_spmm<64, false, true><<<g64, 256>>>(2, 1, 3, vals, cols);
    k_spmm<64, false, true><<<g64, 256>>>(3, 2, 4, vals, cols);
    k_spmm<64, false, true><<<g64, 256>>>(4, 3, 5, vals, cols);
    k_spmm<64, false, true><<<g64, 256>>>(5, 4, 6, vals, cols);
    k_spmm<64, false, true><<<g64, 256>>>(6, 5, 7, vals, cols);

    // h1pre (into d_U term 0) and residual (d_res) — mma.sync tf32
    k_gemm1_mma<<<VV / 64, 256>>>(b1, br);

    k_stats1<<<128, 256>>>();
    k_gnapply1<<<(VV * 128) / 256, 256>>>(g1, be1);

    // block2 Chebyshev terms (D=128): U0..U7
    const int g128 = (VV * 16) / 256;
    k_spmm<128, true, false><<<g128, 256>>>(0, 0, 1, vals, cols);
    k_spmm<128, false, false><<<g128, 256>>>(1, 0, 2, vals, cols);
    k_spmm<128, false, false><<<g128, 256>>>(2, 1, 3, vals, cols);
    k_spmm<128, false, false><<<g128, 256>>>(3, 2, 4, vals, cols);
    k_spmm<128, false, false><<<g128, 256>>>(4, 3, 5, vals, cols);
    k_spmm<128, false, false><<<g128, 256>>>(5, 4, 6, vals, cols);
    k_spmm<128, false, false><<<g128, 256>>>(6, 5, 7, vals, cols);

    // h2pre -> out — mma.sync tf32
    k_gemm2_mma<<<VV / 64, 256>>>(b2, out);

    k_stats2<<<128, 256>>>(out);
    k_final<<<(2 * VV * 64) / 256, 256>>>(out, g2, be2);
}